// round 15
// baseline (speedup 1.0000x reference)
#include <cuda_runtime.h>
#include <cuda_bf16.h>

#define BB 8
#define SS 1024
#define HH 8
#define EE 64
#define NBH (BB*HH)
#define NTOK (BB*SS)

typedef unsigned long long u64;
typedef unsigned int u32;

__device__ __align__(16) float g_attn[NTOK * EE];   // 2 MB scratch

// ---------------------------------------------------------------------------
// helpers
// ---------------------------------------------------------------------------
__device__ __forceinline__ u64 pk2(float lo, float hi) {
    u64 r; asm("mov.b64 %0, {%1, %2};" : "=l"(r) : "f"(lo), "f"(hi)); return r;
}
__device__ __forceinline__ void upk2u(u64 v, u32& lo, u32& hi) {
    asm("mov.b64 {%0, %1}, %2;" : "=r"(lo), "=r"(hi) : "l"(v));
}
__device__ __forceinline__ u64 pfma(u64 a, u64 b, u64 c) {
    u64 d; asm("fma.rn.f32x2 %0, %1, %2, %3;" : "=l"(d) : "l"(a), "l"(b), "l"(c)); return d;
}
__device__ __forceinline__ u64 padd64(u64 a, u64 b) {
    u64 d; asm("add.rn.f32x2 %0, %1, %2;" : "=l"(d) : "l"(a), "l"(b)); return d;
}
__device__ __forceinline__ float ex2(float x) {
    float y; asm("ex2.approx.f32 %0, %1;" : "=f"(y) : "f"(x)); return y;
}
// round fp32 -> tf32 (rna); build phase only
__device__ __forceinline__ u32 cvt_tf32(float f) {
    u32 r; asm("cvt.rna.tf32.f32 %0, %1;" : "=r"(r) : "f"(f)); return r;
}

// m16n8k8 row.col tf32 MMA, fp32 accum (sm_80+ PTX, HMMA fallback)
#define MMA_TF32(d0,d1,d2,d3, a0,a1,a2,a3, b0,b1, c0,c1,c2,c3) \
  asm volatile("mma.sync.aligned.m16n8k8.row.col.f32.tf32.tf32.f32 " \
    "{%0,%1,%2,%3}, {%4,%5,%6,%7}, {%8,%9}, {%10,%11,%12,%13};" \
    : "=f"(d0),"=f"(d1),"=f"(d2),"=f"(d3) \
    : "r"(a0),"r"(a1),"r"(a2),"r"(a3), "r"(b0),"r"(b1), \
      "f"(c0),"f"(c1),"f"(c2),"f"(c3))

#define ONES_TF32 0x3F800000u

// ---------------------------------------------------------------------------
// Fused proj + attention, all-tf32. CTA = (bh, qtile 256), 512 thr.
// 6 MMAs per 16 keys (2 score, 2 AV, 2 den-ones). Weights fed to MMAs raw —
// HW tf32 conversion is identical for numerator and den MMAs (same A regs),
// so no explicit truncation needed. Half the exps computed by packed f32x2
// polynomial (FMA/ALU pipes) to cut the MUFU floor in half.
// ---------------------------------------------------------------------------
#define KSTRIDE 12
#define ATTN_SMEM_BYTES (SS * KSTRIDE * 4)   // 49152

__global__ __launch_bounds__(512, 2) void attn_fused(const float* __restrict__ x,
                                                     const float* __restrict__ theta) {
    extern __shared__ __align__(16) float skf[];   // [1024][12]

    int bh = blockIdx.x;
    int b = bh >> 3, h = bh & 7;
    int qt = blockIdx.y;
    int tid = threadIdx.x;

    float th[8];
#pragma unroll
    for (int i = 0; i < 8; i++) th[i] = __ldg(&theta[i]);

    // ---------------- build phase: keys 2*tid, 2*tid+1 ----------------
    const float* xb = x + (size_t)(b * SS) * 64 + h * 8;
#pragma unroll
    for (int j = 0; j < 2; j++) {
        int s = tid * 2 + j;
        const float4* xs = (const float4*)(xb + (size_t)s * 64);
        float4 v0 = xs[0], v1 = xs[1];
        float a[8] = {v0.x, v0.y, v0.z, v0.w, v1.x, v1.y, v1.z, v1.w};
        float c[8];
#pragma unroll
        for (int i = 0; i < 8; i++) c[i] = __cosf(a[i] + th[i]);
        float p[8];
        p[1] = c[0] * c[1];
#pragma unroll
        for (int w = 2; w < 8; w++) p[w] = p[w - 1] * c[w];
        float qq = c[1];
#pragma unroll
        for (int i = 2; i < 8; i++) qq *= c[i];
        p[0] = qq;
        uint4 w0, w1;
        w0.x = cvt_tf32(p[0]); w0.y = cvt_tf32(p[1]);
        w0.z = cvt_tf32(p[2]); w0.w = cvt_tf32(p[3]);
        w1.x = cvt_tf32(p[4]); w1.y = cvt_tf32(p[5]);
        w1.z = cvt_tf32(p[6]); w1.w = cvt_tf32(p[7]);
        uint4* dst = (uint4*)(skf + s * KSTRIDE);
        dst[0] = w0; dst[1] = w1;
    }
    __syncthreads();

    // ---------------- main loop: warp = 16 queries ----------------
    int lane = tid & 31, warp = tid >> 5;
    int g  = lane >> 2;        // 0..7
    int tc = lane & 3;         // 0..3

    int qbase = qt * 256 + warp * 16;
    int q0 = qbase + g;
    int q1 = q0 + 8;

    const float kexp = 1.4426950408889634f * 0.35355339059327373f;
    u32 A0 = cvt_tf32(skf[q0 * KSTRIDE + tc]     * kexp);
    u32 A1 = cvt_tf32(skf[q1 * KSTRIDE + tc]     * kexp);
    u32 A2 = cvt_tf32(skf[q0 * KSTRIDE + tc + 4] * kexp);
    u32 A3 = cvt_tf32(skf[q1 * KSTRIDE + tc + 4] * kexp);

    // packed exp2 poly constants (loop-invariant)
    const u64 MAGIC2 = pk2(12582912.f, 12582912.f);      // 1.5*2^23
    const u64 NMAGIC2 = pk2(-12582912.f, -12582912.f);
    const u64 NONE2 = pk2(-1.f, -1.f);
    const u64 C4 = pk2(0.009618130f, 0.009618130f);
    const u64 C3 = pk2(0.055504110f, 0.055504110f);
    const u64 C2 = pk2(0.240226507f, 0.240226507f);
    const u64 C1 = pk2(0.693147181f, 0.693147181f);
    const u64 ONE2 = pk2(1.f, 1.f);

    float o0 = 0.f, o1 = 0.f, o2 = 0.f, o3 = 0.f;
    float e0 = 0.f, e1 = 0.f, e2 = 0.f, e3 = 0.f;
    const u32* sku = (const u32*)skf;

#pragma unroll 2
    for (int kb = 0; kb < SS; kb += 16) {
        u32 b10 = sku[(kb + g) * KSTRIDE + tc];
        u32 b11 = sku[(kb + g) * KSTRIDE + tc + 4];
        u32 b20 = sku[(kb + 8 + g) * KSTRIDE + tc];
        u32 b21 = sku[(kb + 8 + g) * KSTRIDE + tc + 4];

        float d10, d11, d12, d13, d20, d21, d22, d23;
        MMA_TF32(d10, d11, d12, d13, A0, A1, A2, A3, b10, b11, 0.f, 0.f, 0.f, 0.f);
        MMA_TF32(d20, d21, d22, d23, A0, A1, A2, A3, b20, b21, 0.f, 0.f, 0.f, 0.f);

        // group 1 weights via packed f32x2 polynomial exp2 (FMA/ALU pipes)
        u32 W10, W11, W12, W13;
        {
            u64 X = pk2(d10, d11);
            u64 t = padd64(X, MAGIC2);
            u64 gg = padd64(t, NMAGIC2);
            u64 f = pfma(gg, NONE2, X);          // f = X - round(X)
            u64 pp = pfma(f, C4, C3);
            pp = pfma(f, pp, C2);
            pp = pfma(f, pp, C1);
            pp = pfma(f, pp, ONE2);              // 2^f
            u32 tl, thi, pl, phi;
            upk2u(t, tl, thi);
            upk2u(pp, pl, phi);
            W10 = pl + (tl << 23);               // * 2^n via exponent add
            W11 = phi + (thi << 23);
        }
        {
            u64 X = pk2(d12, d13);
            u64 t = padd64(X, MAGIC2);
            u64 gg = padd64(t, NMAGIC2);
            u64 f = pfma(gg, NONE2, X);
            u64 pp = pfma(f, C4, C3);
            pp = pfma(f, pp, C2);
            pp = pfma(f, pp, C1);
            pp = pfma(f, pp, ONE2);
            u32 tl, thi, pl, phi;
            upk2u(t, tl, thi);
            upk2u(pp, pl, phi);
            W12 = pl + (tl << 23);
            W13 = phi + (thi << 23);
        }
        // group 2 weights via MUFU
        u32 W20 = __float_as_uint(ex2(d20));
        u32 W21 = __float_as_uint(ex2(d21));
        u32 W22 = __float_as_uint(ex2(d22));
        u32 W23 = __float_as_uint(ex2(d23));

        u32 v10 = sku[(kb + 2 * tc) * KSTRIDE + g];
        u32 v11 = sku[(kb + 2 * tc + 1) * KSTRIDE + g];
        u32 v20 = sku[(kb + 8 + 2 * tc) * KSTRIDE + g];
        u32 v21 = sku[(kb + 8 + 2 * tc + 1) * KSTRIDE + g];

        // numerator (A = permuted score-D weights); HW tf32-truncates A
        MMA_TF32(o0, o1, o2, o3, W10, W12, W11, W13, v10, v11, o0, o1, o2, o3);
        MMA_TF32(o0, o1, o2, o3, W20, W22, W21, W23, v20, v21, o0, o1, o2, o3);
        // denominator: SAME A regs vs ones-B -> identical HW truncation
        MMA_TF32(e0, e1, e2, e3, W10, W12, W11, W13, ONES_TF32, ONES_TF32, e0, e1, e2, e3);
        MMA_TF32(e0, e1, e2, e3, W20, W22, W21, W23, ONES_TF32, ONES_TF32, e0, e1, e2, e3);
    }

    float i0 = __frcp_rn(e0), i1 = __frcp_rn(e2);

    int tok0 = b * SS + q0;
    int tok1 = tok0 + 8;
    float2* o2p = (float2*)g_attn;
    o2p[tok0 * 32 + h * 4 + tc] = make_float2(o0 * i0, o1 * i0);
    o2p[tok1 * 32 + h * 4 + tc] = make_float2(o2 * i1, o3 * i1);
}

// ---------------------------------------------------------------------------
// Kernel 3: out[token, e] = sum_k attn[token, k] * W[e, k]
// grid (256, 2) x 128 thr: CTA = 32 tokens x e-HALF (32 outputs).
// Same total LDS traffic as R14 best, 2x CTAs -> T_CTA halves.
// ---------------------------------------------------------------------------
__global__ __launch_bounds__(128) void combine_kernel(const float* __restrict__ W,
                                                      float* __restrict__ out) {
    __shared__ float wt[EE * 36];        // wt[k*36 + e_local], e-half, padded
    __shared__ float rows[32][68];       // 32 token rows, padded

    int tid = threadIdx.x;
    int eh = blockIdx.y;                 // e-half: 0 or 1

    // W fill: 32 rows (this half) x 16 float4 = 512 float4, 4 per thread
    const float4* W4 = (const float4*)W + eh * 512;
    float4 v[4];
#pragma unroll
    for (int j = 0; j < 4; j++) v[j] = W4[tid + j * 128];
#pragma unroll
    for (int j = 0; j < 4; j++) {
        int idx = tid + j * 128;          // r = idx>>4 (e_local), c = idx&15
        int r = idx >> 4, k0 = (idx & 15) * 4;
        wt[(k0 + 0) * 36 + r] = v[j].x;
        wt[(k0 + 1) * 36 + r] = v[j].y;
        wt[(k0 + 2) * 36 + r] = v[j].z;
        wt[(k0 + 3) * 36 + r] = v[j].w;
    }

    int token0 = blockIdx.x * 32;
    const float4* ga4 = (const float4*)g_attn + token0 * 16;
#pragma unroll
    for (int j = 0; j < 4; j++) {
        int i = tid + j * 128;            // 32 tokens x 16 float4 = 512
        int t = i >> 4, kg = i & 15;
        float4 vv = ga4[i];
        rows[t][kg * 4 + 0] = vv.x; rows[t][kg * 4 + 1] = vv.y;
        rows[t][kg * 4 + 2] = vv.z; rows[t][kg * 4 + 3] = vv.w;
    }
    __syncthreads();

    int tp = tid >> 3;      // token pair 0..15 -> tokens 2tp, 2tp+1
    int og = tid & 7;       // quad within half: outputs eh*32 + og*4 ..
    const ulonglong2* wt2 = (const ulonglong2*)wt;   // 9 units per row

    u64 a0 = 0, a1 = 0, c0 = 0, c1 = 0;
#pragma unroll
    for (int k = 0; k < EE; k++) {
        ulonglong2 bw = wt2[k * 9 + og];
        float r0 = rows[2 * tp + 0][k];
        float r1 = rows[2 * tp + 1][k];
        u64 rr0 = pk2(r0, r0);
        u64 rr1 = pk2(r1, r1);
        a0 = pfma(rr0, bw.x, a0);
        a1 = pfma(rr0, bw.y, a1);
        c0 = pfma(rr1, bw.x, c0);
        c1 = pfma(rr1, bw.y, c1);
    }
    ulonglong2* o2 = (ulonglong2*)out;
    int t0 = token0 + 2 * tp;
    ulonglong2 r0; r0.x = a0; r0.y = a1;
    ulonglong2 r1; r1.x = c0; r1.y = c1;
    o2[(t0 + 0) * 16 + eh * 8 + og] = r0;
    o2[(t0 + 1) * 16 + eh * 8 + og] = r1;
}

// ---------------------------------------------------------------------------
extern "C" void kernel_launch(void* const* d_in, const int* in_sizes, int n_in,
                              void* d_out, int out_size) {
    const float* x      = (const float*)d_in[0];   // [8,1024,64]
    const float* theta  = (const float*)d_in[1];   // [8]
    const float* Wc     = (const float*)d_in[2];   // [64,64]
    float* out          = (float*)d_out;           // [8,1024,64]

    cudaFuncSetAttribute(attn_fused, cudaFuncAttributeMaxDynamicSharedMemorySize,
                         ATTN_SMEM_BYTES);

    dim3 agrid(NBH, SS / 256);
    attn_fused<<<agrid, 512, ATTN_SMEM_BYTES>>>(x, theta);

    dim3 cgrid(NTOK / 32, 2);
    combine_kernel<<<cgrid, 128>>>(Wc, out);
}

// round 16
// speedup vs baseline: 1.0581x; 1.0581x over previous
#include <cuda_runtime.h>
#include <cuda_bf16.h>

#define BB 8
#define SS 1024
#define HH 8
#define EE 64
#define NBH (BB*HH)
#define NTOK (BB*SS)

typedef unsigned long long u64;
typedef unsigned int u32;

__device__ __align__(16) float g_attn[NTOK * EE];   // 2 MB scratch

// ---------------------------------------------------------------------------
// helpers
// ---------------------------------------------------------------------------
__device__ __forceinline__ u64 pk2(float lo, float hi) {
    u64 r; asm("mov.b64 %0, {%1, %2};" : "=l"(r) : "f"(lo), "f"(hi)); return r;
}
__device__ __forceinline__ u64 pfma(u64 a, u64 b, u64 c) {
    u64 d; asm("fma.rn.f32x2 %0, %1, %2, %3;" : "=l"(d) : "l"(a), "l"(b), "l"(c)); return d;
}
__device__ __forceinline__ float ex2(float x) {
    float y; asm("ex2.approx.f32 %0, %1;" : "=f"(y) : "f"(x)); return y;
}
// round fp32 -> tf32 (rna); build phase only
__device__ __forceinline__ u32 cvt_tf32(float f) {
    u32 r; asm("cvt.rna.tf32.f32 %0, %1;" : "=r"(r) : "f"(f)); return r;
}
// scalar exp2 via magic-round + deg-4 poly; immediate constants only
// (FADD-imm / FFMA-imm forms -> ZERO persistent registers). |d| <= 4.1.
__device__ __forceinline__ u32 exp2_poly_bits(float d) {
    float t = d + 12582912.f;          // 1.5*2^23 magic
    float g = t - 12582912.f;          // round(d)
    float f = d - g;                   // frac in [-0.5, 0.5]
    float p = __fmaf_rn(f, 0.0096181291f, 0.0555041087f);
    p = __fmaf_rn(p, f, 0.2402265069f);
    p = __fmaf_rn(p, f, 0.6931471806f);
    p = __fmaf_rn(p, f, 1.0f);         // 2^f
    // n lives in t's low mantissa bits; (t_bits<<23) == n<<23 (mod 2^32)
    return __float_as_uint(p) + (__float_as_uint(t) << 23);
}

// m16n8k8 row.col tf32 MMA, fp32 accum (sm_80+ PTX, HMMA fallback)
#define MMA_TF32(d0,d1,d2,d3, a0,a1,a2,a3, b0,b1, c0,c1,c2,c3) \
  asm volatile("mma.sync.aligned.m16n8k8.row.col.f32.tf32.tf32.f32 " \
    "{%0,%1,%2,%3}, {%4,%5,%6,%7}, {%8,%9}, {%10,%11,%12,%13};" \
    : "=f"(d0),"=f"(d1),"=f"(d2),"=f"(d3) \
    : "r"(a0),"r"(a1),"r"(a2),"r"(a3), "r"(b0),"r"(b1), \
      "f"(c0),"f"(c1),"f"(c2),"f"(c3))

#define ONES_TF32 0x3F800000u

// ---------------------------------------------------------------------------
// Fused proj + attention, all-tf32. CTA = (bh, qtile 256), 512 thr.
// 6 MMAs per 16 keys (2 score, 2 AV, 2 den-ones); weights fed raw (HW tf32
// truncation identical in numerator & den MMAs -> consistent convex ratio).
// 6 exps via MUFU + 2 via register-free scalar poly -> MUFU floor 17.5->13µs.
// ---------------------------------------------------------------------------
#define KSTRIDE 12
#define ATTN_SMEM_BYTES (SS * KSTRIDE * 4)   // 49152

__global__ __launch_bounds__(512, 2) void attn_fused(const float* __restrict__ x,
                                                     const float* __restrict__ theta) {
    extern __shared__ __align__(16) float skf[];   // [1024][12]

    int bh = blockIdx.x;
    int b = bh >> 3, h = bh & 7;
    int qt = blockIdx.y;
    int tid = threadIdx.x;

    float th[8];
#pragma unroll
    for (int i = 0; i < 8; i++) th[i] = __ldg(&theta[i]);

    // ---------------- build phase: keys 2*tid, 2*tid+1 ----------------
    const float* xb = x + (size_t)(b * SS) * 64 + h * 8;
#pragma unroll
    for (int j = 0; j < 2; j++) {
        int s = tid * 2 + j;
        const float4* xs = (const float4*)(xb + (size_t)s * 64);
        float4 v0 = xs[0], v1 = xs[1];
        float a[8] = {v0.x, v0.y, v0.z, v0.w, v1.x, v1.y, v1.z, v1.w};
        float c[8];
#pragma unroll
        for (int i = 0; i < 8; i++) c[i] = __cosf(a[i] + th[i]);
        float p[8];
        p[1] = c[0] * c[1];
#pragma unroll
        for (int w = 2; w < 8; w++) p[w] = p[w - 1] * c[w];
        float qq = c[1];
#pragma unroll
        for (int i = 2; i < 8; i++) qq *= c[i];
        p[0] = qq;
        uint4 w0, w1;
        w0.x = cvt_tf32(p[0]); w0.y = cvt_tf32(p[1]);
        w0.z = cvt_tf32(p[2]); w0.w = cvt_tf32(p[3]);
        w1.x = cvt_tf32(p[4]); w1.y = cvt_tf32(p[5]);
        w1.z = cvt_tf32(p[6]); w1.w = cvt_tf32(p[7]);
        uint4* dst = (uint4*)(skf + s * KSTRIDE);
        dst[0] = w0; dst[1] = w1;
    }
    __syncthreads();

    // ---------------- main loop: warp = 16 queries ----------------
    int lane = tid & 31, warp = tid >> 5;
    int g  = lane >> 2;        // 0..7
    int tc = lane & 3;         // 0..3

    int qbase = qt * 256 + warp * 16;
    int q0 = qbase + g;
    int q1 = q0 + 8;

    const float kexp = 1.4426950408889634f * 0.35355339059327373f;
    u32 A0 = cvt_tf32(skf[q0 * KSTRIDE + tc]     * kexp);
    u32 A1 = cvt_tf32(skf[q1 * KSTRIDE + tc]     * kexp);
    u32 A2 = cvt_tf32(skf[q0 * KSTRIDE + tc + 4] * kexp);
    u32 A3 = cvt_tf32(skf[q1 * KSTRIDE + tc + 4] * kexp);

    float o0 = 0.f, o1 = 0.f, o2 = 0.f, o3 = 0.f;
    float e0 = 0.f, e1 = 0.f, e2 = 0.f, e3 = 0.f;
    const u32* sku = (const u32*)skf;

#pragma unroll 2
    for (int kb = 0; kb < SS; kb += 16) {
        u32 b10 = sku[(kb + g) * KSTRIDE + tc];
        u32 b11 = sku[(kb + g) * KSTRIDE + tc + 4];
        u32 b20 = sku[(kb + 8 + g) * KSTRIDE + tc];
        u32 b21 = sku[(kb + 8 + g) * KSTRIDE + tc + 4];

        float d10, d11, d12, d13, d20, d21, d22, d23;
        MMA_TF32(d10, d11, d12, d13, A0, A1, A2, A3, b10, b11, 0.f, 0.f, 0.f, 0.f);
        MMA_TF32(d20, d21, d22, d23, A0, A1, A2, A3, b20, b21, 0.f, 0.f, 0.f, 0.f);

        // 2 exps on FMA/ALU pipes (register-free poly), 6 on MUFU
        u32 W10 = exp2_poly_bits(d10);
        u32 W11 = exp2_poly_bits(d11);
        u32 W12 = __float_as_uint(ex2(d12));
        u32 W13 = __float_as_uint(ex2(d13));
        u32 W20 = __float_as_uint(ex2(d20));
        u32 W21 = __float_as_uint(ex2(d21));
        u32 W22 = __float_as_uint(ex2(d22));
        u32 W23 = __float_as_uint(ex2(d23));

        u32 v10 = sku[(kb + 2 * tc) * KSTRIDE + g];
        u32 v11 = sku[(kb + 2 * tc + 1) * KSTRIDE + g];
        u32 v20 = sku[(kb + 8 + 2 * tc) * KSTRIDE + g];
        u32 v21 = sku[(kb + 8 + 2 * tc + 1) * KSTRIDE + g];

        // numerator (A = permuted score-D weights); HW tf32-truncates A
        MMA_TF32(o0, o1, o2, o3, W10, W12, W11, W13, v10, v11, o0, o1, o2, o3);
        MMA_TF32(o0, o1, o2, o3, W20, W22, W21, W23, v20, v21, o0, o1, o2, o3);
        // denominator: SAME A regs vs ones-B -> identical truncation
        MMA_TF32(e0, e1, e2, e3, W10, W12, W11, W13, ONES_TF32, ONES_TF32, e0, e1, e2, e3);
        MMA_TF32(e0, e1, e2, e3, W20, W22, W21, W23, ONES_TF32, ONES_TF32, e0, e1, e2, e3);
    }

    float i0 = __frcp_rn(e0), i1 = __frcp_rn(e2);

    int tok0 = b * SS + q0;
    int tok1 = tok0 + 8;
    float2* o2p = (float2*)g_attn;
    o2p[tok0 * 32 + h * 4 + tc] = make_float2(o0 * i0, o1 * i0);
    o2p[tok1 * 32 + h * 4 + tc] = make_float2(o2 * i1, o3 * i1);
}

// ---------------------------------------------------------------------------
// Kernel 3: out[token, e] = sum_k attn[token, k] * W[e, k]
// 256 CTAs x 256 thr x 32 tokens; thread = token-pair x e-quad (R14 best).
// ---------------------------------------------------------------------------
__global__ __launch_bounds__(256) void combine_kernel(const float* __restrict__ W,
                                                      float* __restrict__ out) {
    __shared__ float wt[EE * 68];        // wt[k*68+e] = W[e*64+k], padded rows
    __shared__ float rows[32][68];       // 32 token rows, padded

    int tid = threadIdx.x;

    const float4* W4 = (const float4*)W;
    float4 v[4];
#pragma unroll
    for (int j = 0; j < 4; j++) v[j] = W4[tid + j * 256];
#pragma unroll
    for (int j = 0; j < 4; j++) {
        int idx = tid + j * 256;
        int e = idx >> 4, k0 = (idx & 15) * 4;
        wt[(k0 + 0) * 68 + e] = v[j].x;
        wt[(k0 + 1) * 68 + e] = v[j].y;
        wt[(k0 + 2) * 68 + e] = v[j].z;
        wt[(k0 + 3) * 68 + e] = v[j].w;
    }

    int token0 = blockIdx.x * 32;
    const float4* ga4 = (const float4*)g_attn + token0 * 16;
#pragma unroll
    for (int j = 0; j < 2; j++) {
        int i = tid + j * 256;            // 32 tokens x 16 float4 = 512
        int t = i >> 4, kg = i & 15;
        float4 vv = ga4[i];
        rows[t][kg * 4 + 0] = vv.x; rows[t][kg * 4 + 1] = vv.y;
        rows[t][kg * 4 + 2] = vv.z; rows[t][kg * 4 + 3] = vv.w;
    }
    __syncthreads();

    int tp = tid >> 4;      // token pair 0..15 -> tokens 2tp, 2tp+1
    int og = tid & 15;      // e-quad: outputs og*4 .. og*4+3
    const ulonglong2* wt2 = (const ulonglong2*)wt;   // 17 units per row

    u64 a0 = 0, a1 = 0, c0 = 0, c1 = 0;
#pragma unroll
    for (int k = 0; k < EE; k++) {
        ulonglong2 bw = wt2[k * 17 + og];
        float r0 = rows[2 * tp + 0][k];
        float r1 = rows[2 * tp + 1][k];
        u64 rr0 = pk2(r0, r0);
        u64 rr1 = pk2(r1, r1);
        a0 = pfma(rr0, bw.x, a0);
        a1 = pfma(rr0, bw.y, a1);
        c0 = pfma(rr1, bw.x, c0);
        c1 = pfma(rr1, bw.y, c1);
    }
    ulonglong2* o2 = (ulonglong2*)out;
    int t0 = token0 + 2 * tp;
    ulonglong2 r0; r0.x = a0; r0.y = a1;
    ulonglong2 r1; r1.x = c0; r1.y = c1;
    o2[(t0 + 0) * 16 + og] = r0;
    o2[(t0 + 1) * 16 + og] = r1;
}

// ---------------------------------------------------------------------------
extern "C" void kernel_launch(void* const* d_in, const int* in_sizes, int n_in,
                              void* d_out, int out_size) {
    const float* x      = (const float*)d_in[0];   // [8,1024,64]
    const float* theta  = (const float*)d_in[1];   // [8]
    const float* Wc     = (const float*)d_in[2];   // [64,64]
    float* out          = (float*)d_out;           // [8,1024,64]

    cudaFuncSetAttribute(attn_fused, cudaFuncAttributeMaxDynamicSharedMemorySize,
                         ATTN_SMEM_BYTES);

    dim3 agrid(NBH, SS / 256);
    attn_fused<<<agrid, 512, ATTN_SMEM_BYTES>>>(x, theta);

    combine_kernel<<<NTOK / 32, 256>>>(Wc, out);
}